// round 14
// baseline (speedup 1.0000x reference)
#include <cuda_runtime.h>
#include <cuda_fp16.h>
#include <stdint.h>

// Effective computation (GNN stack is dead code in the reference):
//   z   = x[samples[:,0]] * x[samples[:,1]]          [S, 256]
//   z   = relu(z @ lin1_W + lin1_b)                  [S, 256]
//   out = z @ lin2_W + lin2_b                        [S, 2]
//
// R13: fp16 mma.sync (m16n8k16, f32 accum), 256 threads, warp tile 64x64.
// Gather DRAM latency removed from the critical path: raw x slices are
// cp.async'd into smem ~2 chunks ahead (per-thread wait_group — each thread
// consumes only its own bytes). Product/cvt/STS runs from smem. B fragments
// register-prefetched one kk-step ahead. Double-buffered A smem.

#define KD  256
#define BM  128
#define KC  32
#define NCH 8

#define ABUF    10240            // per-buffer A: 128 rows x 80B
#define RAW_OFF 20480
#define RSTG    36864            // raw stage: 256 threads x 144B
#define DSMEM   (RAW_OFF + 2 * RSTG)   // 94208

// W1 fp16 fragments: [kk_global 16][ntile 32][lane 32] -> uint2 {b0, b1}
__device__ uint2 g_Wf[16 * 32 * 32];

__device__ __forceinline__ uint32_t pack_f16x2(float lo, float hi) {
    uint32_t r;   // low 16 <- lo
    asm("cvt.rn.f16x2.f32 %0, %1, %2;" : "=r"(r) : "f"(hi), "f"(lo));
    return r;
}

__global__ void conv_w_kernel(const float* __restrict__ W1) {
    const int idx  = blockIdx.x * 256 + threadIdx.x;   // 16384 total
    const int lane = idx & 31;
    const int tile = (idx >> 5) & 31;
    const int kkg  = idx >> 10;                        // 0..15
    const int n  = tile * 8 + (lane >> 2);
    const int k0 = kkg * 16 + (lane & 3) * 2;
    const float w00 = W1[(size_t)k0 * KD + n];
    const float w01 = W1[(size_t)(k0 + 1) * KD + n];
    const float w10 = W1[(size_t)(k0 + 8) * KD + n];
    const float w11 = W1[(size_t)(k0 + 9) * KD + n];
    g_Wf[idx] = make_uint2(pack_f16x2(w00, w01), pack_f16x2(w10, w11));
}

__device__ __forceinline__ uint32_t smem_u32(const void* p) {
    uint32_t a;
    asm("{ .reg .u64 t; cvta.to.shared.u64 t, %1; cvt.u32.u64 %0, t; }"
        : "=r"(a) : "l"(p));
    return a;
}

#define CP16(saddr, gptr) \
    asm volatile("cp.async.cg.shared.global [%0], [%1], 16;" \
        :: "r"(saddr), "l"(gptr) : "memory")
#define CP_COMMIT() asm volatile("cp.async.commit_group;" ::: "memory")
#define CP_WAIT(n)  asm volatile("cp.async.wait_group %0;" :: "n"(n) : "memory")

#define LDSM4(r, addr) \
    asm volatile("ldmatrix.sync.aligned.m8n8.x4.shared.b16 {%0,%1,%2,%3}, [%4];" \
        : "=r"((r)[0]), "=r"((r)[1]), "=r"((r)[2]), "=r"((r)[3]) : "r"(addr))

#define MMA_F16(c, a, b0, b1) \
    asm volatile("mma.sync.aligned.m16n8k16.row.col.f32.f16.f16.f32 " \
        "{%0,%1,%2,%3}, {%4,%5,%6,%7}, {%8,%9}, {%0,%1,%2,%3};" \
        : "+f"((c)[0]), "+f"((c)[1]), "+f"((c)[2]), "+f"((c)[3]) \
        : "r"((a)[0]), "r"((a)[1]), "r"((a)[2]), "r"((a)[3]), "r"(b0), "r"(b1))

#define LOAD_WB(wB, kkg) do { \
    const uint2* _p = g_Wf + (kkg) * 1024 + nw * 256 + lane; \
    _Pragma("unroll") \
    for (int tn = 0; tn < 8; ++tn) (wB)[tn] = _p[tn * 32]; \
    } while (0)

// one kk-step: LDSM A for 4 m16 tiles, 32 MMAs with B set wB
#define KK_STEP(aAddr, wB) do { \
    uint32_t a[4][4]; \
    LDSM4(a[0], (aAddr)); \
    LDSM4(a[1], (aAddr) + 1280); \
    LDSM4(a[2], (aAddr) + 2560); \
    LDSM4(a[3], (aAddr) + 3840); \
    _Pragma("unroll") \
    for (int tn = 0; tn < 8; ++tn) { \
        _Pragma("unroll") \
        for (int tm = 0; tm < 4; ++tm) \
            MMA_F16(acc[tm][tn], a[tm], (wB)[tn].x, (wB)[tn].y); \
    } } while (0)

// product + fp16 pack + STS from a raw smem slice (thread-private bytes)
#define BUILD_A(rsrc, abufp) do { \
    _Pragma("unroll") \
    for (int g = 0; g < 2; ++g) { \
        const float4 a0 = *(const float4*)((rsrc) + g * 32); \
        const float4 a1 = *(const float4*)((rsrc) + g * 32 + 16); \
        const float4 b0 = *(const float4*)((rsrc) + 64 + g * 32); \
        const float4 b1 = *(const float4*)((rsrc) + 64 + g * 32 + 16); \
        uint4 h; \
        h.x = pack_f16x2(a0.x * b0.x, a0.y * b0.y); \
        h.y = pack_f16x2(a0.z * b0.z, a0.w * b0.w); \
        h.z = pack_f16x2(a1.x * b1.x, a1.y * b1.y); \
        h.w = pack_f16x2(a1.z * b1.z, a1.w * b1.w); \
        *(uint4*)((abufp) + stsOff + g * 16) = h; \
    } } while (0)

__global__ __launch_bounds__(256, 1) void fused_pair_mlp_mma(
    const float* __restrict__ x,
    const void*  __restrict__ samples_raw,
    const float* __restrict__ b1,
    const float* __restrict__ W2,
    const float* __restrict__ b2,
    float* __restrict__ out,
    int S, int n_nodes)
{
    extern __shared__ __align__(16) char dsm[];   // A bufs + raw stages
    __shared__ float  sb1[256];
    __shared__ float2 sw2[256];
    __shared__ float2 red[BM * 4];

    const uint32_t sb = smem_u32(dsm);
    const int tid  = threadIdx.x;
    const int lane = tid & 31;
    const int wid  = tid >> 5;
    const int mw   = wid >> 2;      // 0..1 (M 2x64)
    const int nw   = wid & 3;       // 0..3 (N 4x64)
    const int m0   = blockIdx.x * BM;

    sb1[tid] = b1[tid];
    sw2[tid] = *(const float2*)&W2[tid * 2];

    // ---- dtype detection: int64 vs int32 sample indices (uniform)
    const long long* s64 = (const long long*)samples_raw;
    const int*       s32 = (const int*)samples_raw;
    bool is64 = true;
#pragma unroll
    for (int i = 0; i < 4; ++i) {
        long long v = __ldg(&s64[i]);
        if (v < 0 || v >= (long long)n_nodes) is64 = false;
    }

    // ---- A staging map: thread t -> row t>>1 (0..127), 16 k's at (t&1)*16
    const int arow = tid >> 1;
    const int half = tid & 1;
    int gr = m0 + arow; if (gr >= S) gr = S - 1;
    long long ia, ib;
    if (is64) { ia = s64[(long long)gr * 2]; ib = s64[(long long)gr * 2 + 1]; }
    else      { ia = s32[gr * 2];            ib = s32[gr * 2 + 1]; }
    const float* xa = x + ia * KD + half * 16;
    const float* xb = x + ib * KD + half * 16;
    const uint32_t stsOff = (uint32_t)(arow * 80 + half * 32);  // 16 fp16 = 32B

    // raw-stage per-thread base (144B stride -> LDS.128 conflict-free)
    const uint32_t rb0 = sb + RAW_OFF + (uint32_t)tid * 144;            // stage 0
    const char*    rp0 = dsm + RAW_OFF + tid * 144;

    // ---- ldmatrix A per-lane base (row-major m16 tiles, 80B row stride)
    const uint32_t aLane =
        2u * ((mw * 64 + (lane & 15)) * 40 + ((lane >> 4) << 3));

    float acc[4][8][4];
#pragma unroll
    for (int i = 0; i < 4; ++i)
#pragma unroll
        for (int j = 0; j < 8; ++j)
#pragma unroll
            for (int p = 0; p < 4; ++p) acc[i][j][p] = 0.f;

    uint2 wBa[8], wBb[8];

    // ---- prologue: cp.async chunk0 -> stage0, chunk1 -> stage1
#pragma unroll
    for (int i = 0; i < 4; ++i) {
        CP16(rb0 + i * 16,      xa + i * 4);
        CP16(rb0 + 64 + i * 16, xb + i * 4);
    }
    CP_COMMIT();
#pragma unroll
    for (int i = 0; i < 4; ++i) {
        CP16(rb0 + RSTG + i * 16,      xa + KC + i * 4);
        CP16(rb0 + RSTG + 64 + i * 16, xb + KC + i * 4);
    }
    CP_COMMIT();
    LOAD_WB(wBa, 0);
    CP_WAIT(1);                       // chunk0 raw landed
    BUILD_A(rp0, dsm);                // A-buf 0
    __syncthreads();

    // ---- K loop: 8 chunks of 32 (2 kk-steps each)
#pragma unroll 1
    for (int c = 0; c < NCH; ++c) {
        const int buf = c & 1;
        const uint32_t aBase = sb + buf * ABUF + aLane;
        const bool more = (c + 1 < NCH);

        // kk0 with wBa | prefetch wBb = (c, kk1)
        LOAD_WB(wBb, c * 2 + 1);
        KK_STEP(aBase, wBa);

        if (more) {
            // issue cp.async for chunk c+2 into stage c&1 (read last chunk)
            if (c + 2 < NCH) {
                const uint32_t rdst = rb0 + (uint32_t)(c & 1) * RSTG;
                const float* pa = xa + (c + 2) * KC;
                const float* pb = xb + (c + 2) * KC;
#pragma unroll
                for (int i = 0; i < 4; ++i) {
                    CP16(rdst + i * 16,      pa + i * 4);
                    CP16(rdst + 64 + i * 16, pb + i * 4);
                }
                CP_COMMIT();
                CP_WAIT(1);           // chunk c+1 raw landed (c+2 in flight)
            } else {
                CP_WAIT(0);           // last raw chunk
            }
            // build next A buffer from raw stage (c+1)&1
            const char* rsrc = rp0 + ((c + 1) & 1) * RSTG;
            char* db = dsm + (buf ^ 1) * ABUF;
            BUILD_A(rsrc, db);
            LOAD_WB(wBa, c * 2 + 2);
        }

        // kk1 with wBb
        KK_STEP(aBase + 32, wBb);

        if (more) __syncthreads();
    }

    // ---- epilogue: bias + relu + [256,2] GEMM, warp-reduce then smem combine
    const int lr = lane >> 2;
    const int lc = (lane & 3) * 2;
#pragma unroll
    for (int tm = 0; tm < 4; ++tm) {
#pragma unroll
        for (int hh = 0; hh < 2; ++hh) {
            const int row = mw * 64 + tm * 16 + lr + hh * 8;
            float o0 = 0.f, o1 = 0.f;
#pragma unroll
            for (int tn = 0; tn < 8; ++tn) {
                const int cb = nw * 64 + tn * 8 + lc;
                const float z0 = fmaxf(acc[tm][tn][hh * 2 + 0] + sb1[cb], 0.f);
                const float z1 = fmaxf(acc[tm][tn][hh * 2 + 1] + sb1[cb + 1], 0.f);
                const float2 w0 = sw2[cb];
                const float2 w1 = sw2[cb + 1];
                o0 = fmaf(z0, w0.x, fmaf(z1, w1.x, o0));
                o1 = fmaf(z0, w0.y, fmaf(z1, w1.y, o1));
            }
            o0 += __shfl_xor_sync(0xffffffffu, o0, 1);
            o0 += __shfl_xor_sync(0xffffffffu, o0, 2);
            o1 += __shfl_xor_sync(0xffffffffu, o1, 1);
            o1 += __shfl_xor_sync(0xffffffffu, o1, 2);
            if ((lane & 3) == 0) red[row * 4 + nw] = make_float2(o0, o1);
        }
    }
    __syncthreads();

    if (tid < BM) {
        const int m = m0 + tid;
        if (m < S) {
            float2 s = red[tid * 4];
#pragma unroll
            for (int p = 1; p < 4; ++p) {
                s.x += red[tid * 4 + p].x;
                s.y += red[tid * 4 + p].y;
            }
            float2 o;
            o.x = s.x + b2[0];
            o.y = s.y + b2[1];
            *(float2*)(out + m * 2) = o;
        }
    }
}

extern "C" void kernel_launch(void* const* d_in, const int* in_sizes, int n_in,
                              void* d_out, int out_size) {
    // metadata order: x_feature, edge_index, samples, W1, b1, W2, b2,
    //                 lin1_W, lin1_b, lin2_W, lin2_b
    const float* x       = (const float*)d_in[0];
    const void*  samples = d_in[2];
    const float* lin1_W  = (const float*)d_in[7];
    const float* lin1_b  = (const float*)d_in[8];
    const float* lin2_W  = (const float*)d_in[9];
    const float* lin2_b  = (const float*)d_in[10];
    float* out = (float*)d_out;

    const int S       = in_sizes[2] / 2;
    const int n_nodes = in_sizes[0] / KD;
    const int grid    = (S + BM - 1) / BM;

    conv_w_kernel<<<64, 256>>>(lin1_W);

    cudaFuncSetAttribute(fused_pair_mlp_mma,
                         cudaFuncAttributeMaxDynamicSharedMemorySize, DSMEM);
    fused_pair_mlp_mma<<<grid, 256, DSMEM>>>(
        x, samples, lin1_b, lin2_W, lin2_b, out, S, n_nodes);
}

// round 15
// speedup vs baseline: 1.3462x; 1.3462x over previous
#include <cuda_runtime.h>
#include <cuda_fp16.h>
#include <stdint.h>

// Effective computation (GNN stack is dead code in the reference):
//   z   = x[samples[:,0]] * x[samples[:,1]]          [S, 256]
//   z   = relu(z @ lin1_W + lin1_b)                  [S, 256]
//   out = z @ lin2_W + lin2_b                        [S, 2]
//
// R14: fp16 mma.sync (m16n8k16, f32 accum), 256 threads, warp tile 64x64,
// BM=128. W1's entire fp16 fragment image (128KB) is made SMEM-RESIDENT in
// the prologue (cp.async) -> the mainloop has NO B LDG; B fragments come
// from 29-cyc LDS.64, register-prefetched one kk-step ahead (fully hidden).
// A gather register-prefetched one chunk ahead. Double-buffered A smem.

#define KD  256
#define BM  128
#define KC  32
#define NCH 8

#define ABUF   10240             // per-buffer A: 128 rows x 80B
#define BOFF   (2 * ABUF)        // 20480
#define BBYTES 131072            // full W1 fragment image
#define DSMEM  (BOFF + BBYTES)   // 151552

// W1 fp16 fragments: [kk_global 16][ntile 32][lane 32] -> uint2 {b0, b1}
__device__ uint2 g_Wf[16 * 32 * 32];

__device__ __forceinline__ uint32_t pack_f16x2(float lo, float hi) {
    uint32_t r;   // low 16 <- lo
    asm("cvt.rn.f16x2.f32 %0, %1, %2;" : "=r"(r) : "f"(hi), "f"(lo));
    return r;
}

__global__ void conv_w_kernel(const float* __restrict__ W1) {
    const int idx  = blockIdx.x * 256 + threadIdx.x;   // 16384 total
    const int lane = idx & 31;
    const int tile = (idx >> 5) & 31;
    const int kkg  = idx >> 10;                        // 0..15
    const int n  = tile * 8 + (lane >> 2);
    const int k0 = kkg * 16 + (lane & 3) * 2;
    const float w00 = W1[(size_t)k0 * KD + n];
    const float w01 = W1[(size_t)(k0 + 1) * KD + n];
    const float w10 = W1[(size_t)(k0 + 8) * KD + n];
    const float w11 = W1[(size_t)(k0 + 9) * KD + n];
    g_Wf[idx] = make_uint2(pack_f16x2(w00, w01), pack_f16x2(w10, w11));
}

__device__ __forceinline__ uint32_t smem_u32(const void* p) {
    uint32_t a;
    asm("{ .reg .u64 t; cvta.to.shared.u64 t, %1; cvt.u32.u64 %0, t; }"
        : "=r"(a) : "l"(p));
    return a;
}

#define CP16(saddr, gptr) \
    asm volatile("cp.async.cg.shared.global [%0], [%1], 16;" \
        :: "r"(saddr), "l"(gptr) : "memory")
#define CP_COMMIT() asm volatile("cp.async.commit_group;" ::: "memory")
#define CP_WAIT0()  asm volatile("cp.async.wait_group 0;" ::: "memory")

#define LDSM4(r, addr) \
    asm volatile("ldmatrix.sync.aligned.m8n8.x4.shared.b16 {%0,%1,%2,%3}, [%4];" \
        : "=r"((r)[0]), "=r"((r)[1]), "=r"((r)[2]), "=r"((r)[3]) : "r"(addr))

#define MMA_F16(c, a, b0, b1) \
    asm volatile("mma.sync.aligned.m16n8k16.row.col.f32.f16.f16.f32 " \
        "{%0,%1,%2,%3}, {%4,%5,%6,%7}, {%8,%9}, {%0,%1,%2,%3};" \
        : "+f"((c)[0]), "+f"((c)[1]), "+f"((c)[2]), "+f"((c)[3]) \
        : "r"((a)[0]), "r"((a)[1]), "r"((a)[2]), "r"((a)[3]), "r"(b0), "r"(b1))

// B fragments from SMEM (29-cyc LDS.64, conflict-free: lane*8 stride)
#define LOAD_WB(wB, kkg) do { \
    const char* _p = dsm + BOFF + (kkg) * 8192 + nw * 2048 + lane * 8; \
    _Pragma("unroll") \
    for (int tn = 0; tn < 8; ++tn) (wB)[tn] = *(const uint2*)(_p + tn * 256); \
    } while (0)

// one kk-step: LDSM A for 4 m16 tiles, 32 MMAs with B set wB
#define KK_STEP(aAddr, wB) do { \
    uint32_t a[4][4]; \
    LDSM4(a[0], (aAddr)); \
    LDSM4(a[1], (aAddr) + 1280); \
    LDSM4(a[2], (aAddr) + 2560); \
    LDSM4(a[3], (aAddr) + 3840); \
    _Pragma("unroll") \
    for (int tn = 0; tn < 8; ++tn) { \
        _Pragma("unroll") \
        for (int tm = 0; tm < 4; ++tm) \
            MMA_F16(acc[tm][tn], a[tm], (wB)[tn].x, (wB)[tn].y); \
    } } while (0)

__global__ __launch_bounds__(256, 1) void fused_pair_mlp_mma(
    const float* __restrict__ x,
    const void*  __restrict__ samples_raw,
    const float* __restrict__ b1,
    const float* __restrict__ W2,
    const float* __restrict__ b2,
    float* __restrict__ out,
    int S, int n_nodes)
{
    extern __shared__ __align__(16) char dsm[];   // A bufs + resident B
    __shared__ float  sb1[256];
    __shared__ float2 sw2[256];
    __shared__ float2 red[BM * 4];

    const uint32_t sb = smem_u32(dsm);
    const int tid  = threadIdx.x;
    const int lane = tid & 31;
    const int wid  = tid >> 5;
    const int mw   = wid >> 2;      // 0..1 (M 2x64)
    const int nw   = wid & 3;       // 0..3 (N 4x64)
    const int m0   = blockIdx.x * BM;

    sb1[tid] = b1[tid];
    sw2[tid] = *(const float2*)&W2[tid * 2];

    // ---- prologue part 1: cp.async the full B fragment image into smem
    {
        const char* gW = (const char*)g_Wf + tid * 16;
        const uint32_t bdst = sb + BOFF + (uint32_t)tid * 16;
#pragma unroll
        for (int i = 0; i < 32; ++i)
            CP16(bdst + i * 4096, gW + i * 4096);
        CP_COMMIT();
    }

    // ---- dtype detection: int64 vs int32 sample indices (uniform)
    const long long* s64 = (const long long*)samples_raw;
    const int*       s32 = (const int*)samples_raw;
    bool is64 = true;
#pragma unroll
    for (int i = 0; i < 4; ++i) {
        long long v = __ldg(&s64[i]);
        if (v < 0 || v >= (long long)n_nodes) is64 = false;
    }

    // ---- A staging map: thread t -> row t>>1 (0..127), 16 k's at (t&1)*16
    const int arow = tid >> 1;
    const int half = tid & 1;
    int gr = m0 + arow; if (gr >= S) gr = S - 1;
    long long ia, ib;
    if (is64) { ia = s64[(long long)gr * 2]; ib = s64[(long long)gr * 2 + 1]; }
    else      { ia = s32[gr * 2];            ib = s32[gr * 2 + 1]; }
    const float* xa = x + ia * KD + half * 16;
    const float* xb = x + ib * KD + half * 16;
    const uint32_t stsOff = (uint32_t)(arow * 80 + half * 32);  // 16 fp16 = 32B

    // ---- ldmatrix A per-lane base (row-major m16 tiles, 80B row stride)
    const uint32_t aLane =
        2u * ((mw * 64 + (lane & 15)) * 40 + ((lane >> 4) << 3));

    float acc[4][8][4];
#pragma unroll
    for (int i = 0; i < 4; ++i)
#pragma unroll
        for (int j = 0; j < 8; ++j)
#pragma unroll
            for (int p = 0; p < 4; ++p) acc[i][j][p] = 0.f;

    uint2 wBa[8], wBb[8];

    // ---- prologue part 2: stage A chunk 0 (16 k's/thread) into buf 0
    {
        const float4 va0 = *(const float4*)xa;
        const float4 va1 = *(const float4*)(xa + 4);
        const float4 va2 = *(const float4*)(xa + 8);
        const float4 va3 = *(const float4*)(xa + 12);
        const float4 vb0 = *(const float4*)xb;
        const float4 vb1 = *(const float4*)(xb + 4);
        const float4 vb2 = *(const float4*)(xb + 8);
        const float4 vb3 = *(const float4*)(xb + 12);
        uint4 h0, h1;
        h0.x = pack_f16x2(va0.x * vb0.x, va0.y * vb0.y);
        h0.y = pack_f16x2(va0.z * vb0.z, va0.w * vb0.w);
        h0.z = pack_f16x2(va1.x * vb1.x, va1.y * vb1.y);
        h0.w = pack_f16x2(va1.z * vb1.z, va1.w * vb1.w);
        h1.x = pack_f16x2(va2.x * vb2.x, va2.y * vb2.y);
        h1.y = pack_f16x2(va2.z * vb2.z, va2.w * vb2.w);
        h1.z = pack_f16x2(va3.x * vb3.x, va3.y * vb3.y);
        h1.w = pack_f16x2(va3.z * vb3.z, va3.w * vb3.w);
        *(uint4*)(dsm + stsOff)      = h0;
        *(uint4*)(dsm + stsOff + 16) = h1;
    }
    CP_WAIT0();            // B image resident
    __syncthreads();       // A buf0 + B visible to all
    LOAD_WB(wBa, 0);

    // ---- K loop: 8 chunks of 32 (2 kk-steps each)
#pragma unroll 1
    for (int c = 0; c < NCH; ++c) {
        const int buf = c & 1;
        const uint32_t aBase = sb + buf * ABUF + aLane;
        const bool more = (c + 1 < NCH);

        // next chunk's gather loads (latency hidden under kk0's 32 MMAs)
        float4 va0, va1, va2, va3, vb0, vb1, vb2, vb3;
        if (more) {
            const int o = (c + 1) * KC;
            va0 = *(const float4*)(xa + o);      va1 = *(const float4*)(xa + o + 4);
            va2 = *(const float4*)(xa + o + 8);  va3 = *(const float4*)(xa + o + 12);
            vb0 = *(const float4*)(xb + o);      vb1 = *(const float4*)(xb + o + 4);
            vb2 = *(const float4*)(xb + o + 8);  vb3 = *(const float4*)(xb + o + 12);
        }

        // kk0 with wBa | prefetch wBb = (c, kk1) via LDS
        LOAD_WB(wBb, c * 2 + 1);
        KK_STEP(aBase, wBa);

        // stage next chunk's A into the other buffer
        if (more) {
            uint4 h0, h1;
            h0.x = pack_f16x2(va0.x * vb0.x, va0.y * vb0.y);
            h0.y = pack_f16x2(va0.z * vb0.z, va0.w * vb0.w);
            h0.z = pack_f16x2(va1.x * vb1.x, va1.y * vb1.y);
            h0.w = pack_f16x2(va1.z * vb1.z, va1.w * vb1.w);
            h1.x = pack_f16x2(va2.x * vb2.x, va2.y * vb2.y);
            h1.y = pack_f16x2(va2.z * vb2.z, va2.w * vb2.w);
            h1.z = pack_f16x2(va3.x * vb3.x, va3.y * vb3.y);
            h1.w = pack_f16x2(va3.z * vb3.z, va3.w * vb3.w);
            char* db = dsm + (buf ^ 1) * ABUF;
            *(uint4*)(db + stsOff)      = h0;
            *(uint4*)(db + stsOff + 16) = h1;
        }

        // kk1 with wBb | prefetch wBa = (c+1, kk0) via LDS
        if (more) LOAD_WB(wBa, c * 2 + 2);
        KK_STEP(aBase + 32, wBb);

        if (more) __syncthreads();
    }

    // ---- epilogue: bias + relu + [256,2] GEMM, warp-reduce then smem combine
    const int lr = lane >> 2;
    const int lc = (lane & 3) * 2;
#pragma unroll
    for (int tm = 0; tm < 4; ++tm) {
#pragma unroll
        for (int hh = 0; hh < 2; ++hh) {
            const int row = mw * 64 + tm * 16 + lr + hh * 8;
            float o0 = 0.f, o1 = 0.f;
#pragma unroll
            for (int tn = 0; tn < 8; ++tn) {
                const int cb = nw * 64 + tn * 8 + lc;
                const float z0 = fmaxf(acc[tm][tn][hh * 2 + 0] + sb1[cb], 0.f);
                const float z1 = fmaxf(acc[tm][tn][hh * 2 + 1] + sb1[cb + 1], 0.f);
                const float2 w0 = sw2[cb];
                const float2 w1 = sw2[cb + 1];
                o0 = fmaf(z0, w0.x, fmaf(z1, w1.x, o0));
                o1 = fmaf(z0, w0.y, fmaf(z1, w1.y, o1));
            }
            o0 += __shfl_xor_sync(0xffffffffu, o0, 1);
            o0 += __shfl_xor_sync(0xffffffffu, o0, 2);
            o1 += __shfl_xor_sync(0xffffffffu, o1, 1);
            o1 += __shfl_xor_sync(0xffffffffu, o1, 2);
            if ((lane & 3) == 0) red[row * 4 + nw] = make_float2(o0, o1);
        }
    }
    __syncthreads();

    if (tid < BM) {
        const int m = m0 + tid;
        if (m < S) {
            float2 s = red[tid * 4];
#pragma unroll
            for (int p = 1; p < 4; ++p) {
                s.x += red[tid * 4 + p].x;
                s.y += red[tid * 4 + p].y;
            }
            float2 o;
            o.x = s.x + b2[0];
            o.y = s.y + b2[1];
            *(float2*)(out + m * 2) = o;
        }
    }
}

extern "C" void kernel_launch(void* const* d_in, const int* in_sizes, int n_in,
                              void* d_out, int out_size) {
    // metadata order: x_feature, edge_index, samples, W1, b1, W2, b2,
    //                 lin1_W, lin1_b, lin2_W, lin2_b
    const float* x       = (const float*)d_in[0];
    const void*  samples = d_in[2];
    const float* lin1_W  = (const float*)d_in[7];
    const float* lin1_b  = (const float*)d_in[8];
    const float* lin2_W  = (const float*)d_in[9];
    const float* lin2_b  = (const float*)d_in[10];
    float* out = (float*)d_out;

    const int S       = in_sizes[2] / 2;
    const int n_nodes = in_sizes[0] / KD;
    const int grid    = (S + BM - 1) / BM;

    conv_w_kernel<<<64, 256>>>(lin1_W);

    cudaFuncSetAttribute(fused_pair_mlp_mma,
                         cudaFuncAttributeMaxDynamicSharedMemorySize, DSMEM);
    fused_pair_mlp_mma<<<grid, 256, DSMEM>>>(
        x, samples, lin1_b, lin2_W, lin2_b, out, S, n_nodes);
}